// round 4
// baseline (speedup 1.0000x reference)
#include <cuda_runtime.h>
#include <math.h>
#include <stdint.h>

#define NTOK 16384
#define DMODEL 1024
#define FF 4096
#define NEXP 8
#define CAP 2560
#define NA (NTOK*2)

// ---------------- device scratch (static, allocation-free) ----------------
__device__ float g_buf[(size_t)NEXP*CAP*DMODEL];   //  84 MB dispatch buffer
__device__ float g_h  [(size_t)NEXP*CAP*FF];       // 335 MB hidden activations
__device__ float g_y  [(size_t)NEXP*CAP*DMODEL];   //  84 MB expert outputs
__device__ int   g_topi[NA];
__device__ float g_topv[NA];
__device__ int   g_apos[NA];
__device__ int   g_slot_a[NEXP*CAP];
__device__ int   g_kept[NEXP];

__device__ __forceinline__ uint32_t f2tf32(float f) {
    uint32_t u; asm("cvt.rna.tf32.f32 %0, %1;" : "=r"(u) : "f"(f)); return u;
}
__device__ __forceinline__ void mma_tf32(float* d, const uint32_t* a, const uint32_t* b) {
    asm volatile("mma.sync.aligned.m16n8k8.row.col.f32.tf32.tf32.f32 "
        "{%0,%1,%2,%3}, {%4,%5,%6,%7}, {%8,%9}, {%0,%1,%2,%3};"
        : "+f"(d[0]), "+f"(d[1]), "+f"(d[2]), "+f"(d[3])
        : "r"(a[0]), "r"(a[1]), "r"(a[2]), "r"(a[3]), "r"(b[0]), "r"(b[1]));
}

// ---------------- tf32 tensor-core grouped GEMM ----------------
// C[z] = A[z](MxK rm) @ B[z](KxN rm) + bias[z], optional exact GELU.
// CTA tile 256(M)x128(N), k-chunk 16, 8 warps (4m x 2n), warp tile 64x64.
// SMEM: A[2][256][16] XOR-swizzled (k ^ (((row>>1)&3)<<2)),
//       B[2][16][128] XOR-swizzled (n ^ ((k&3)<<3)). 48KB total, conflict-free.
__global__ void __launch_bounds__(256, 1) moe_mma_kernel(
    const float* __restrict__ Ab, const float* __restrict__ Bb,
    const float* __restrict__ biasb, float* __restrict__ Cb,
    int N, int K, int gelu_flag,
    long sA, long sB, long sBias, long sC)
{
    __shared__ float As[2][256 * 16];   // 32 KB
    __shared__ float Bs[2][16 * 128];   // 16 KB

    const float* A = Ab + (size_t)blockIdx.z * sA;
    const float* B = Bb + (size_t)blockIdx.z * sB;
    const float* bias = biasb + (size_t)blockIdx.z * sBias;
    float* C = Cb + (size_t)blockIdx.z * sC;

    const int tid = threadIdx.x;
    const int wid = tid >> 5, lane = tid & 31;
    const int wm = wid >> 1;          // 0..3 -> m offset wm*64
    const int wn = wid & 1;           // 0..1 -> n offset wn*64
    const int g = lane >> 2;          // 0..7
    const int t = lane & 3;           // 0..3
    const int bm = blockIdx.y * 256;
    const int bn = blockIdx.x * 128;

    // staging coords
    const int a_row = tid >> 2;               // +l*64, l=0..3
    const int a_k4  = (tid & 3) * 4;
    const int sw_a  = ((a_row >> 1) & 3) << 2;    // invariant under +64
    const int b_kr  = tid >> 5;               // +l*8, l=0..1
    const int b_n4  = (tid & 31) * 4;
    const int sw_b  = (b_kr & 3) << 3;            // invariant under +8

    // fragment-read swizzles
    const int sw_fa = ((g >> 1) & 3) << 2;        // A frag k-swizzle
    const int sw_fb = t << 3;                      // B frag n-swizzle

    float acc[4][8][4];
#pragma unroll
    for (int mt = 0; mt < 4; mt++)
#pragma unroll
        for (int nt = 0; nt < 8; nt++)
#pragma unroll
            for (int q = 0; q < 4; q++) acc[mt][nt][q] = 0.f;

    const int nch = K >> 4;
    float4 pa[4], pb[2];

    // prefetch chunk 0
    {
        const float* Ag = A + (size_t)bm * K;
        const float* Bg = B + bn;
#pragma unroll
        for (int l = 0; l < 4; l++)
            pa[l] = *(const float4*)(Ag + (size_t)(a_row + l * 64) * K + a_k4);
#pragma unroll
        for (int l = 0; l < 2; l++)
            pb[l] = *(const float4*)(Bg + (size_t)(b_kr + l * 8) * N + b_n4);
    }
    // store chunk 0
#pragma unroll
    for (int l = 0; l < 4; l++) {
        uint32_t u[4] = { f2tf32(pa[l].x), f2tf32(pa[l].y), f2tf32(pa[l].z), f2tf32(pa[l].w) };
        *(uint4*)&As[0][(a_row + l * 64) * 16 + (a_k4 ^ sw_a)] = make_uint4(u[0], u[1], u[2], u[3]);
    }
#pragma unroll
    for (int l = 0; l < 2; l++) {
        uint32_t u[4] = { f2tf32(pb[l].x), f2tf32(pb[l].y), f2tf32(pb[l].z), f2tf32(pb[l].w) };
        *(uint4*)&Bs[0][(b_kr + l * 8) * 128 + (b_n4 ^ sw_b)] = make_uint4(u[0], u[1], u[2], u[3]);
    }
    __syncthreads();

    for (int i = 0; i < nch; i++) {
        const int buf = i & 1;
        // prefetch next chunk (global -> regs)
        if (i + 1 < nch) {
            const int k0 = (i + 1) << 4;
            const float* Ag = A + (size_t)bm * K + k0;
            const float* Bg = B + (size_t)k0 * N + bn;
#pragma unroll
            for (int l = 0; l < 4; l++)
                pa[l] = *(const float4*)(Ag + (size_t)(a_row + l * 64) * K + a_k4);
#pragma unroll
            for (int l = 0; l < 2; l++)
                pb[l] = *(const float4*)(Bg + (size_t)(b_kr + l * 8) * N + b_n4);
        }
        // compute current chunk
        const float* as = As[buf];
        const float* bs = Bs[buf];
#pragma unroll
        for (int kk = 0; kk < 2; kk++) {
            const int kb = kk * 8 + t;
            const int k1 = kb ^ sw_fa;
            const int k2 = (kb ^ 4) ^ sw_fa;
            uint32_t af[4][4], bf[8][2];
#pragma unroll
            for (int mt = 0; mt < 4; mt++) {
                const int rb = (wm * 64 + mt * 16 + g) * 16;
                af[mt][0] = __float_as_uint(as[rb + k1]);
                af[mt][1] = __float_as_uint(as[rb + 128 + k1]);   // +8 rows
                af[mt][2] = __float_as_uint(as[rb + k2]);
                af[mt][3] = __float_as_uint(as[rb + 128 + k2]);
            }
#pragma unroll
            for (int nt = 0; nt < 8; nt++) {
                const int nx = (wn * 64 + nt * 8 + g) ^ sw_fb;
                bf[nt][0] = __float_as_uint(bs[kb * 128 + nx]);
                bf[nt][1] = __float_as_uint(bs[(kb + 4) * 128 + nx]);
            }
#pragma unroll
            for (int mt = 0; mt < 4; mt++)
#pragma unroll
                for (int nt = 0; nt < 8; nt++)
                    mma_tf32(acc[mt][nt], af[mt], bf[nt]);
        }
        // stage next chunk to smem
        if (i + 1 < nch) {
            const int nb = buf ^ 1;
#pragma unroll
            for (int l = 0; l < 4; l++) {
                uint32_t u[4] = { f2tf32(pa[l].x), f2tf32(pa[l].y), f2tf32(pa[l].z), f2tf32(pa[l].w) };
                *(uint4*)&As[nb][(a_row + l * 64) * 16 + (a_k4 ^ sw_a)] = make_uint4(u[0], u[1], u[2], u[3]);
            }
#pragma unroll
            for (int l = 0; l < 2; l++) {
                uint32_t u[4] = { f2tf32(pb[l].x), f2tf32(pb[l].y), f2tf32(pb[l].z), f2tf32(pb[l].w) };
                *(uint4*)&Bs[nb][(b_kr + l * 8) * 128 + (b_n4 ^ sw_b)] = make_uint4(u[0], u[1], u[2], u[3]);
            }
            __syncthreads();
        }
    }

    // ---- epilogue: bias + optional exact GELU, float2 stores ----
#pragma unroll
    for (int mt = 0; mt < 4; mt++) {
        const int row = bm + wm * 64 + mt * 16 + g;
#pragma unroll
        for (int nt = 0; nt < 8; nt++) {
            const int col = bn + wn * 64 + nt * 8 + 2 * t;
            const float bz0 = bias[col], bz1 = bias[col + 1];
            float v[4] = { acc[mt][nt][0] + bz0, acc[mt][nt][1] + bz1,
                           acc[mt][nt][2] + bz0, acc[mt][nt][3] + bz1 };
            if (gelu_flag) {
#pragma unroll
                for (int q = 0; q < 4; q++)
                    v[q] = 0.5f * v[q] * (1.0f + erff(v[q] * 0.70710678118654752f));
            }
            *(float2*)(C + (size_t)row * N + col)       = make_float2(v[0], v[1]);
            *(float2*)(C + (size_t)(row + 8) * N + col) = make_float2(v[2], v[3]);
        }
    }
}

// ---------------- router: logits -> softmax -> top2 ----------------
__global__ void __launch_bounds__(256) router_kernel(const float* __restrict__ x,
                                                     const float* __restrict__ wr,
                                                     const float* __restrict__ br) {
    __shared__ float swT[NEXP][DMODEL];
    int tid = threadIdx.x;
    for (int i = tid; i < DMODEL * NEXP; i += 256) {
        int d = i >> 3, e = i & 7;
        swT[e][d] = wr[i];
    }
    __syncthreads();
    int warp = tid >> 5, lane = tid & 31;
    int token = blockIdx.x * 8 + warp;
    const float* xr = x + (size_t)token * DMODEL;
    float p[NEXP];
#pragma unroll
    for (int e = 0; e < NEXP; e++) p[e] = 0.f;
    for (int j = lane; j < DMODEL; j += 32) {
        float xv = xr[j];
#pragma unroll
        for (int e = 0; e < NEXP; e++) p[e] = fmaf(xv, swT[e][j], p[e]);
    }
#pragma unroll
    for (int e = 0; e < NEXP; e++) {
#pragma unroll
        for (int off = 16; off; off >>= 1)
            p[e] += __shfl_xor_sync(0xffffffffu, p[e], off);
    }
    if (lane == 0) {
        float mx = -1e30f;
#pragma unroll
        for (int e = 0; e < NEXP; e++) { p[e] += br[e]; mx = fmaxf(mx, p[e]); }
        float s = 0.f;
#pragma unroll
        for (int e = 0; e < NEXP; e++) { p[e] = expf(p[e] - mx); s += p[e]; }
        float inv = 1.f / s;
#pragma unroll
        for (int e = 0; e < NEXP; e++) p[e] *= inv;
        int b0 = 0; float v0 = p[0];
#pragma unroll
        for (int e = 1; e < NEXP; e++) if (p[e] > v0) { v0 = p[e]; b0 = e; }
        int b1 = -1; float v1 = -1.f;
#pragma unroll
        for (int e = 0; e < NEXP; e++) if (e != b0 && p[e] > v1) { v1 = p[e]; b1 = e; }
        g_topi[token*2]   = b0;  g_topv[token*2]   = v0;
        g_topi[token*2+1] = b1;  g_topv[token*2+1] = v1;
    }
}

// ---------------- arrival-order capacity scan ----------------
__global__ void __launch_bounds__(1024) scan_kernel() {
    __shared__ int scnt[1024][NEXP];
    int tid = threadIdx.x;
    int cnt[NEXP];
#pragma unroll
    for (int e = 0; e < NEXP; e++) cnt[e] = 0;
    int a0 = tid * 32;
    for (int i = 0; i < 32; i++) cnt[g_topi[a0 + i]]++;
#pragma unroll
    for (int e = 0; e < NEXP; e++) scnt[tid][e] = cnt[e];
    __syncthreads();
    if (tid < NEXP) {
        int run = 0;
        for (int i = 0; i < 1024; i++) { int tv = scnt[i][tid]; scnt[i][tid] = run; run += tv; }
        g_kept[tid] = run < CAP ? run : CAP;
    }
    __syncthreads();
    int base[NEXP];
#pragma unroll
    for (int e = 0; e < NEXP; e++) base[e] = scnt[tid][e];
    for (int i = 0; i < 32; i++) {
        int a = a0 + i;
        int e = g_topi[a];
        int pos = base[e]++;
        if (pos < CAP) { g_apos[a] = pos; g_slot_a[e * CAP + pos] = a; }
        else           { g_apos[a] = -1; }
    }
}

// ---------------- dispatch gather ----------------
__global__ void __launch_bounds__(256) dispatch_kernel(const float* __restrict__ x) {
    int r = blockIdx.x;
    int e = r / CAP, pos = r - e * CAP;
    float4* dst = (float4*)(g_buf + (size_t)r * DMODEL);
    if (pos < g_kept[e]) {
        int a = g_slot_a[r];
        const float4* src = (const float4*)(x + (size_t)(a >> 1) * DMODEL);
        dst[threadIdx.x] = src[threadIdx.x];
    } else {
        dst[threadIdx.x] = make_float4(0.f, 0.f, 0.f, 0.f);
    }
}

// ---------------- combine ----------------
__global__ void __launch_bounds__(256) combine_kernel(float* __restrict__ out) {
    int token = blockIdx.x;
    int a0 = token * 2;
    int p0 = g_apos[a0], p1 = g_apos[a0 + 1];
    float w0 = (p0 >= 0) ? g_topv[a0]     : 0.f;
    float w1 = (p1 >= 0) ? g_topv[a0 + 1] : 0.f;
    float ws = w0 + w1;
    int t4 = threadIdx.x;
    float4 acc = make_float4(0.f, 0.f, 0.f, 0.f);
    if (p0 >= 0) {
        const float4* r = (const float4*)(g_y + ((size_t)g_topi[a0] * CAP + p0) * DMODEL);
        float4 v = r[t4];
        acc.x = fmaf(w0, v.x, acc.x); acc.y = fmaf(w0, v.y, acc.y);
        acc.z = fmaf(w0, v.z, acc.z); acc.w = fmaf(w0, v.w, acc.w);
    }
    if (p1 >= 0) {
        const float4* r = (const float4*)(g_y + ((size_t)g_topi[a0 + 1] * CAP + p1) * DMODEL);
        float4 v = r[t4];
        acc.x = fmaf(w1, v.x, acc.x); acc.y = fmaf(w1, v.y, acc.y);
        acc.z = fmaf(w1, v.z, acc.z); acc.w = fmaf(w1, v.w, acc.w);
    }
    if (ws > 0.f) {
        float inv = 1.f / fmaxf(ws, 1e-6f);
        acc.x *= inv; acc.y *= inv; acc.z *= inv; acc.w *= inv;
    }
    ((float4*)(out + (size_t)token * DMODEL))[t4] = acc;
}

// ---------------- launch ----------------
extern "C" void kernel_launch(void* const* d_in, const int* in_sizes, int n_in,
                              void* d_out, int out_size) {
    const float* x  = (const float*)d_in[0];
    const float* wr = (const float*)d_in[1];
    const float* br = (const float*)d_in[2];
    const float* w1 = (const float*)d_in[3];
    const float* b1 = (const float*)d_in[4];
    const float* w2 = (const float*)d_in[5];
    const float* b2 = (const float*)d_in[6];
    float* y = (float*)d_out;

    float *buf, *h, *yy;
    cudaGetSymbolAddress((void**)&buf, g_buf);
    cudaGetSymbolAddress((void**)&h,   g_h);
    cudaGetSymbolAddress((void**)&yy,  g_y);

    router_kernel<<<NTOK / 8, 256>>>(x, wr, br);
    scan_kernel<<<1, 1024>>>();
    dispatch_kernel<<<NEXP * CAP, 256>>>(x);

    // GEMM1: h = GELU(buf @ w1 + b1)   [per expert: 2560x1024 @ 1024x4096]
    dim3 g1(FF / 128, CAP / 256, NEXP);       // 32 x 10 x 8
    moe_mma_kernel<<<g1, 256>>>(buf, w1, b1, h, FF, DMODEL, 1,
                              (long)CAP * DMODEL, (long)DMODEL * FF, FF, (long)CAP * FF);

    // GEMM2: y_e = h @ w2 + b2          [per expert: 2560x4096 @ 4096x1024]
    dim3 g2(DMODEL / 128, CAP / 256, NEXP);   // 8 x 10 x 8
    moe_mma_kernel<<<g2, 256>>>(h, w2, b2, yy, DMODEL, FF, 0,
                              (long)CAP * FF, (long)FF * DMODEL, DMODEL, (long)CAP * DMODEL);

    combine_kernel<<<NTOK, 256>>>(y);
}

// round 5
// speedup vs baseline: 1.2092x; 1.2092x over previous
#include <cuda_runtime.h>
#include <math.h>
#include <stdint.h>

#define NTOK 16384
#define DMODEL 1024
#define FF 4096
#define NEXP 8
#define CAP 2560
#define NA (NTOK*2)

// ---------------- device scratch (static, allocation-free) ----------------
__device__ float g_buf[(size_t)NEXP*CAP*DMODEL];   //  84 MB dispatch buffer (tf32-rounded)
__device__ float g_h  [(size_t)NEXP*CAP*FF];       // 335 MB hidden activations (tf32-rounded)
__device__ float g_y  [(size_t)NEXP*CAP*DMODEL];   //  84 MB expert outputs
__device__ float g_w1t[(size_t)NEXP*DMODEL*FF];    // 128 MB tf32-rounded w1
__device__ float g_w2t[(size_t)NEXP*FF*DMODEL];    // 128 MB tf32-rounded w2
__device__ int   g_topi[NA];
__device__ float g_topv[NA];
__device__ int   g_apos[NA];
__device__ int   g_slot_a[NEXP*CAP];
__device__ int   g_kept[NEXP];

__device__ __forceinline__ uint32_t f2tf32(float f) {
    uint32_t u; asm("cvt.rna.tf32.f32 %0, %1;" : "=r"(u) : "f"(f)); return u;
}
__device__ __forceinline__ float roundtf(float f) { return __uint_as_float(f2tf32(f)); }

__device__ __forceinline__ void mma_tf32(float* d, const uint32_t* a, const uint32_t* b) {
    asm volatile("mma.sync.aligned.m16n8k8.row.col.f32.tf32.tf32.f32 "
        "{%0,%1,%2,%3}, {%4,%5,%6,%7}, {%8,%9}, {%0,%1,%2,%3};"
        : "+f"(d[0]), "+f"(d[1]), "+f"(d[2]), "+f"(d[3])
        : "r"(a[0]), "r"(a[1]), "r"(a[2]), "r"(a[3]), "r"(b[0]), "r"(b[1]));
}
__device__ __forceinline__ uint32_t smem_u32(const void* p) {
    uint32_t a;
    asm("{ .reg .u64 t; cvta.to.shared.u64 t, %1; cvt.u32.u64 %0, t; }" : "=r"(a) : "l"(p));
    return a;
}
__device__ __forceinline__ void cp16(uint32_t dst, const float* src) {
    asm volatile("cp.async.cg.shared.global [%0], [%1], 16;" :: "r"(dst), "l"(src) : "memory");
}
#define CP_COMMIT() asm volatile("cp.async.commit_group;" ::: "memory")
#define CP_WAIT2()  asm volatile("cp.async.wait_group 2;" ::: "memory")

// ---------------- tf32 tensor-core grouped GEMM, 4-stage cp.async pipeline --------
// C[z] = A[z](MxK rm) @ B[z](KxN rm) + bias[z].  flags: bit0=exact GELU, bit1=round out to tf32.
// Inputs A,B must already be tf32-rounded (cp.async copies raw bits).
// CTA tile 256(M)x128(N), k-chunk 16, 8 warps (4m x 2n), warp tile 64x64.
// Stage = A[256][16] (sw: k ^ (((row>>1)&3)<<2)) + B[16][128] (sw: n ^ ((k&3)<<3)); 24KB x 4.
#define STAGE_FLOATS 6144
#define STAGE_BYTES  24576

__global__ void __launch_bounds__(256, 1) moe_mma_kernel(
    const float* __restrict__ Ab, const float* __restrict__ Bb,
    const float* __restrict__ biasb, float* __restrict__ Cb,
    int N, int K, int flags,
    long sA, long sB, long sBias, long sC)
{
    extern __shared__ float smem[];
    const uint32_t sbase = smem_u32(smem);

    const float* A = Ab + (size_t)blockIdx.z * sA;
    const float* B = Bb + (size_t)blockIdx.z * sB;
    const float* bias = biasb + (size_t)blockIdx.z * sBias;
    float* C = Cb + (size_t)blockIdx.z * sC;

    const int tid = threadIdx.x;
    const int wid = tid >> 5, lane = tid & 31;
    const int wm = wid >> 1;          // 0..3 -> m offset wm*64
    const int wn = wid & 1;           // 0..1 -> n offset wn*64
    const int g = lane >> 2;          // 0..7
    const int t = lane & 3;           // 0..3
    const int bm = blockIdx.y * 256;
    const int bn = blockIdx.x * 128;

    // staging coords
    const int a_row = tid >> 2;                   // +l*64
    const int a_k4  = (tid & 3) * 4;
    const int a_k4s = a_k4 ^ (((a_row >> 1) & 3) << 2);   // swizzle invariant under +64
    const int b_kr  = tid >> 5;                   // +l*8
    const int b_n4  = (tid & 31) * 4;
    const int b_n4s = b_n4 ^ ((b_kr & 3) << 3);           // swizzle invariant under +8

    // fragment-read swizzles
    const int sw_fa = ((g >> 1) & 3) << 2;
    const int sw_fb = t << 3;

    float acc[4][8][4];
#pragma unroll
    for (int mt = 0; mt < 4; mt++)
#pragma unroll
        for (int nt = 0; nt < 8; nt++)
#pragma unroll
            for (int q = 0; q < 4; q++) acc[mt][nt][q] = 0.f;

    const int nch = K >> 4;
    const float* Agb = A + (size_t)(bm + a_row) * K + a_k4;   // + k0 per chunk
    const float* Bgb = B + (size_t)b_kr * N + bn + b_n4;      // + k0*N per chunk

    // prologue: issue stages 0..2
#pragma unroll
    for (int s = 0; s < 3; s++) {
        const int k0 = s << 4;
        uint32_t ab = sbase + s * STAGE_BYTES;
        const float* Ag = Agb + k0;
#pragma unroll
        for (int l = 0; l < 4; l++)
            cp16(ab + (uint32_t)(((a_row + l * 64) * 16 + a_k4s) * 4), Ag + (size_t)l * 64 * K);
        uint32_t bb = ab + 16384;
        const float* Bg = Bgb + (size_t)k0 * N;
#pragma unroll
        for (int l = 0; l < 2; l++)
            cp16(bb + (uint32_t)(((b_kr + l * 8) * 128 + b_n4s) * 4), Bg + (size_t)l * 8 * N);
        CP_COMMIT();
    }
    CP_WAIT2();
    __syncthreads();

    for (int i = 0; i < nch; i++) {
        const int slot = i & 3;
        // issue chunk i+3 (or empty group to keep wait_group accounting aligned)
        if (i + 3 < nch) {
            const int k0 = (i + 3) << 4;
            uint32_t ab = sbase + ((i + 3) & 3) * STAGE_BYTES;
            const float* Ag = Agb + k0;
#pragma unroll
            for (int l = 0; l < 4; l++)
                cp16(ab + (uint32_t)(((a_row + l * 64) * 16 + a_k4s) * 4), Ag + (size_t)l * 64 * K);
            uint32_t bb = ab + 16384;
            const float* Bg = Bgb + (size_t)k0 * N;
#pragma unroll
            for (int l = 0; l < 2; l++)
                cp16(bb + (uint32_t)(((b_kr + l * 8) * 128 + b_n4s) * 4), Bg + (size_t)l * 8 * N);
        }
        CP_COMMIT();

        // compute current chunk
        const float* as = smem + slot * STAGE_FLOATS;
        const float* bs = as + 4096;
#pragma unroll
        for (int kk = 0; kk < 2; kk++) {
            const int kb = kk * 8 + t;
            const int k1 = kb ^ sw_fa;
            const int k2 = (kb ^ 4) ^ sw_fa;
            uint32_t af[4][4], bf[8][2];
#pragma unroll
            for (int mt = 0; mt < 4; mt++) {
                const int rb = (wm * 64 + mt * 16 + g) * 16;
                af[mt][0] = __float_as_uint(as[rb + k1]);
                af[mt][1] = __float_as_uint(as[rb + 128 + k1]);
                af[mt][2] = __float_as_uint(as[rb + k2]);
                af[mt][3] = __float_as_uint(as[rb + 128 + k2]);
            }
#pragma unroll
            for (int nt = 0; nt < 8; nt++) {
                const int nx = (wn * 64 + nt * 8 + g) ^ sw_fb;
                bf[nt][0] = __float_as_uint(bs[kb * 128 + nx]);
                bf[nt][1] = __float_as_uint(bs[(kb + 4) * 128 + nx]);
            }
#pragma unroll
            for (int mt = 0; mt < 4; mt++)
#pragma unroll
                for (int nt = 0; nt < 8; nt++)
                    mma_tf32(acc[mt][nt], af[mt], bf[nt]);
        }
        CP_WAIT2();
        __syncthreads();
    }

    // ---- epilogue: bias + optional exact GELU (+ optional tf32 rounding), float2 stores ----
    const int do_gelu = flags & 1, do_round = flags & 2;
#pragma unroll
    for (int mt = 0; mt < 4; mt++) {
        const int row = bm + wm * 64 + mt * 16 + g;
#pragma unroll
        for (int nt = 0; nt < 8; nt++) {
            const int col = bn + wn * 64 + nt * 8 + 2 * t;
            const float bz0 = bias[col], bz1 = bias[col + 1];
            float v[4] = { acc[mt][nt][0] + bz0, acc[mt][nt][1] + bz1,
                           acc[mt][nt][2] + bz0, acc[mt][nt][3] + bz1 };
            if (do_gelu) {
#pragma unroll
                for (int q = 0; q < 4; q++)
                    v[q] = 0.5f * v[q] * (1.0f + erff(v[q] * 0.70710678118654752f));
            }
            if (do_round) {
#pragma unroll
                for (int q = 0; q < 4; q++) v[q] = roundtf(v[q]);
            }
            *(float2*)(C + (size_t)row * N + col)       = make_float2(v[0], v[1]);
            *(float2*)(C + (size_t)(row + 8) * N + col) = make_float2(v[2], v[3]);
        }
    }
}

// ---------------- weight pre-round (fp32 -> tf32-rounded fp32 bits) ----------------
__global__ void __launch_bounds__(256) round_tf32_kernel(const float4* __restrict__ in,
                                                         float4* __restrict__ out, int n4) {
    int i = blockIdx.x * 256 + threadIdx.x;
    if (i < n4) {
        float4 v = in[i];
        v.x = roundtf(v.x); v.y = roundtf(v.y); v.z = roundtf(v.z); v.w = roundtf(v.w);
        out[i] = v;
    }
}

// ---------------- router: logits -> softmax -> top2 ----------------
__global__ void __launch_bounds__(256) router_kernel(const float* __restrict__ x,
                                                     const float* __restrict__ wr,
                                                     const float* __restrict__ br) {
    __shared__ float swT[NEXP][DMODEL];
    int tid = threadIdx.x;
    for (int i = tid; i < DMODEL * NEXP; i += 256) {
        int d = i >> 3, e = i & 7;
        swT[e][d] = wr[i];
    }
    __syncthreads();
    int warp = tid >> 5, lane = tid & 31;
    int token = blockIdx.x * 8 + warp;
    const float* xr = x + (size_t)token * DMODEL;
    float p[NEXP];
#pragma unroll
    for (int e = 0; e < NEXP; e++) p[e] = 0.f;
    for (int j = lane; j < DMODEL; j += 32) {
        float xv = xr[j];
#pragma unroll
        for (int e = 0; e < NEXP; e++) p[e] = fmaf(xv, swT[e][j], p[e]);
    }
#pragma unroll
    for (int e = 0; e < NEXP; e++) {
#pragma unroll
        for (int off = 16; off; off >>= 1)
            p[e] += __shfl_xor_sync(0xffffffffu, p[e], off);
    }
    if (lane == 0) {
        float mx = -1e30f;
#pragma unroll
        for (int e = 0; e < NEXP; e++) { p[e] += br[e]; mx = fmaxf(mx, p[e]); }
        float s = 0.f;
#pragma unroll
        for (int e = 0; e < NEXP; e++) { p[e] = expf(p[e] - mx); s += p[e]; }
        float inv = 1.f / s;
#pragma unroll
        for (int e = 0; e < NEXP; e++) p[e] *= inv;
        int b0 = 0; float v0 = p[0];
#pragma unroll
        for (int e = 1; e < NEXP; e++) if (p[e] > v0) { v0 = p[e]; b0 = e; }
        int b1 = -1; float v1 = -1.f;
#pragma unroll
        for (int e = 0; e < NEXP; e++) if (e != b0 && p[e] > v1) { v1 = p[e]; b1 = e; }
        g_topi[token*2]   = b0;  g_topv[token*2]   = v0;
        g_topi[token*2+1] = b1;  g_topv[token*2+1] = v1;
    }
}

// ---------------- arrival-order capacity scan ----------------
__global__ void __launch_bounds__(1024) scan_kernel() {
    __shared__ int scnt[1024][NEXP];
    int tid = threadIdx.x;
    int cnt[NEXP];
#pragma unroll
    for (int e = 0; e < NEXP; e++) cnt[e] = 0;
    int a0 = tid * 32;
    for (int i = 0; i < 32; i++) cnt[g_topi[a0 + i]]++;
#pragma unroll
    for (int e = 0; e < NEXP; e++) scnt[tid][e] = cnt[e];
    __syncthreads();
    if (tid < NEXP) {
        int run = 0;
        for (int i = 0; i < 1024; i++) { int tv = scnt[i][tid]; scnt[i][tid] = run; run += tv; }
        g_kept[tid] = run < CAP ? run : CAP;
    }
    __syncthreads();
    int base[NEXP];
#pragma unroll
    for (int e = 0; e < NEXP; e++) base[e] = scnt[tid][e];
    for (int i = 0; i < 32; i++) {
        int a = a0 + i;
        int e = g_topi[a];
        int pos = base[e]++;
        if (pos < CAP) { g_apos[a] = pos; g_slot_a[e * CAP + pos] = a; }
        else           { g_apos[a] = -1; }
    }
}

// ---------------- dispatch gather (writes tf32-rounded activations) ----------------
__global__ void __launch_bounds__(256) dispatch_kernel(const float* __restrict__ x) {
    int r = blockIdx.x;
    int e = r / CAP, pos = r - e * CAP;
    float4* dst = (float4*)(g_buf + (size_t)r * DMODEL);
    if (pos < g_kept[e]) {
        int a = g_slot_a[r];
        const float4* src = (const float4*)(x + (size_t)(a >> 1) * DMODEL);
        float4 v = src[threadIdx.x];
        v.x = roundtf(v.x); v.y = roundtf(v.y); v.z = roundtf(v.z); v.w = roundtf(v.w);
        dst[threadIdx.x] = v;
    } else {
        dst[threadIdx.x] = make_float4(0.f, 0.f, 0.f, 0.f);
    }
}

// ---------------- combine ----------------
__global__ void __launch_bounds__(256) combine_kernel(float* __restrict__ out) {
    int token = blockIdx.x;
    int a0 = token * 2;
    int p0 = g_apos[a0], p1 = g_apos[a0 + 1];
    float w0 = (p0 >= 0) ? g_topv[a0]     : 0.f;
    float w1 = (p1 >= 0) ? g_topv[a0 + 1] : 0.f;
    float ws = w0 + w1;
    int t4 = threadIdx.x;
    float4 acc = make_float4(0.f, 0.f, 0.f, 0.f);
    if (p0 >= 0) {
        const float4* r = (const float4*)(g_y + ((size_t)g_topi[a0] * CAP + p0) * DMODEL);
        float4 v = r[t4];
        acc.x = fmaf(w0, v.x, acc.x); acc.y = fmaf(w0, v.y, acc.y);
        acc.z = fmaf(w0, v.z, acc.z); acc.w = fmaf(w0, v.w, acc.w);
    }
    if (p1 >= 0) {
        const float4* r = (const float4*)(g_y + ((size_t)g_topi[a0 + 1] * CAP + p1) * DMODEL);
        float4 v = r[t4];
        acc.x = fmaf(w1, v.x, acc.x); acc.y = fmaf(w1, v.y, acc.y);
        acc.z = fmaf(w1, v.z, acc.z); acc.w = fmaf(w1, v.w, acc.w);
    }
    if (ws > 0.f) {
        float inv = 1.f / fmaxf(ws, 1e-6f);
        acc.x *= inv; acc.y *= inv; acc.z *= inv; acc.w *= inv;
    }
    ((float4*)(out + (size_t)token * DMODEL))[t4] = acc;
}

// ---------------- launch ----------------
#define SMEM_TOTAL (4 * STAGE_BYTES)

extern "C" void kernel_launch(void* const* d_in, const int* in_sizes, int n_in,
                              void* d_out, int out_size) {
    const float* x  = (const float*)d_in[0];
    const float* wr = (const float*)d_in[1];
    const float* br = (const float*)d_in[2];
    const float* w1 = (const float*)d_in[3];
    const float* b1 = (const float*)d_in[4];
    const float* w2 = (const float*)d_in[5];
    const float* b2 = (const float*)d_in[6];
    float* y = (float*)d_out;

    float *buf, *h, *yy, *w1t, *w2t;
    cudaGetSymbolAddress((void**)&buf, g_buf);
    cudaGetSymbolAddress((void**)&h,   g_h);
    cudaGetSymbolAddress((void**)&yy,  g_y);
    cudaGetSymbolAddress((void**)&w1t, g_w1t);
    cudaGetSymbolAddress((void**)&w2t, g_w2t);

    cudaFuncSetAttribute(moe_mma_kernel, cudaFuncAttributeMaxDynamicSharedMemorySize, SMEM_TOTAL);

    const int wn4 = NEXP * DMODEL * FF / 4;
    round_tf32_kernel<<<(wn4 + 255) / 256, 256>>>((const float4*)w1, (float4*)w1t, wn4);
    round_tf32_kernel<<<(wn4 + 255) / 256, 256>>>((const float4*)w2, (float4*)w2t, wn4);

    router_kernel<<<NTOK / 8, 256>>>(x, wr, br);
    scan_kernel<<<1, 1024>>>();
    dispatch_kernel<<<NEXP * CAP, 256>>>(x);

    // GEMM1: h = round_tf32(GELU(buf @ w1 + b1))   [per expert: 2560x1024 @ 1024x4096]
    dim3 g1(FF / 128, CAP / 256, NEXP);       // 32 x 10 x 8
    moe_mma_kernel<<<g1, 256, SMEM_TOTAL>>>(buf, w1t, b1, h, FF, DMODEL, 3,
                              (long)CAP * DMODEL, (long)DMODEL * FF, FF, (long)CAP * FF);

    // GEMM2: y_e = h @ w2 + b2                      [per expert: 2560x4096 @ 4096x1024]
    dim3 g2(DMODEL / 128, CAP / 256, NEXP);   // 8 x 10 x 8
    moe_mma_kernel<<<g2, 256, SMEM_TOTAL>>>(h, w2t, b2, yy, DMODEL, FF, 0,
                              (long)CAP * FF, (long)FF * DMODEL, DMODEL, (long)CAP * DMODEL);

    combine_kernel<<<NTOK, 256>>>(y);
}

// round 6
// speedup vs baseline: 2.0502x; 1.6955x over previous
#include <cuda_runtime.h>
#include <cuda_fp16.h>
#include <math.h>
#include <stdint.h>

#define NTOK 16384
#define DMODEL 1024
#define FF 4096
#define NEXP 8
#define CAP 2560
#define NA (NTOK*2)

// ---------------- device scratch (static, allocation-free) ----------------
__device__ __half g_buf[(size_t)NEXP*CAP*DMODEL];   //  42 MB dispatched activations (fp16)
__device__ __half g_h  [(size_t)NEXP*CAP*FF];       // 168 MB hidden activations (fp16)
__device__ float  g_y  [(size_t)NEXP*CAP*DMODEL];   //  84 MB expert outputs (fp32)
__device__ __half g_w1h[(size_t)NEXP*DMODEL*FF];    //  64 MB w1 fp16, transposed [E][FF][DMODEL]
__device__ __half g_w2h[(size_t)NEXP*FF*DMODEL];    //  64 MB w2 fp16, transposed [E][DMODEL][FF]
__device__ int   g_topi[NA];
__device__ float g_topv[NA];
__device__ int   g_apos[NA];
__device__ int   g_slot_a[NEXP*CAP];
__device__ int   g_kept[NEXP];

__device__ __forceinline__ void mma_f16(float* d, const uint32_t* a, const uint32_t* b) {
    asm volatile("mma.sync.aligned.m16n8k16.row.col.f32.f16.f16.f32 "
        "{%0,%1,%2,%3}, {%4,%5,%6,%7}, {%8,%9}, {%0,%1,%2,%3};"
        : "+f"(d[0]), "+f"(d[1]), "+f"(d[2]), "+f"(d[3])
        : "r"(a[0]), "r"(a[1]), "r"(a[2]), "r"(a[3]), "r"(b[0]), "r"(b[1]));
}
__device__ __forceinline__ uint32_t smem_u32(const void* p) {
    uint32_t a;
    asm("{ .reg .u64 t; cvta.to.shared.u64 t, %1; cvt.u32.u64 %0, t; }" : "=r"(a) : "l"(p));
    return a;
}
__device__ __forceinline__ void cp16(uint32_t dst, const void* src) {
    asm volatile("cp.async.cg.shared.global [%0], [%1], 16;" :: "r"(dst), "l"(src) : "memory");
}
#define CP_COMMIT() asm volatile("cp.async.commit_group;" ::: "memory")
#define CP_WAIT2()  asm volatile("cp.async.wait_group 2;" ::: "memory")

// ---------------- fp16 tensor-core grouped GEMM, 4-stage cp.async pipeline --------
// C[z] = A[z](MxK rm fp16) @ B[z]^T (B stored [N][K] rm fp16) + bias[z].
// flags: bit0 = exact GELU, bit1 = fp16 output (else fp32).
// CTA tile 256(M)x128(N), k-chunk 32, 8 warps (4m x 2n), warp tile 64x64.
// Stage: A[256 rows][32 fp16] + B[128 rows][32 fp16]; rows = 64B = 4 x 16B chunks,
// chunk c stored at (c ^ ((row>>1)&3)) -> conflict-free fragment reads.
#define STAGE_BYTES 24576

__global__ void __launch_bounds__(256, 1) moe_mma_kernel(
    const __half* __restrict__ Ab, const __half* __restrict__ Bb,
    const float* __restrict__ biasb, void* __restrict__ Cb,
    int N, int K, int flags,
    long sA, long sB, long sBias, long sC)
{
    extern __shared__ char smem[];
    const uint32_t sbase = smem_u32(smem);

    const __half* A = Ab + (size_t)blockIdx.z * sA;
    const __half* B = Bb + (size_t)blockIdx.z * sB;
    const float* bias = biasb + (size_t)blockIdx.z * sBias;

    const int tid = threadIdx.x;
    const int wid = tid >> 5, lane = tid & 31;
    const int wm = wid >> 1;          // 0..3 -> m offset wm*64
    const int wn = wid & 1;           // 0..1 -> n offset wn*64
    const int g = lane >> 2;          // 0..7
    const int t = lane & 3;           // 0..3
    const int bm = blockIdx.y * 256;
    const int bn = blockIdx.x * 128;

    // staging coords: thread i -> row (i>>2)+l*64, 16B chunk (i&3)
    const int s_row = tid >> 2;                       // 0..63
    const int s_c   = tid & 3;
    const int s_cs  = s_c ^ ((s_row >> 1) & 3);       // swizzled chunk (invariant under +64)
    const int swz   = (g >> 1) & 3;                   // fragment-read chunk swizzle

    float acc[4][8][4];
#pragma unroll
    for (int mt = 0; mt < 4; mt++)
#pragma unroll
        for (int nt = 0; nt < 8; nt++)
#pragma unroll
            for (int q = 0; q < 4; q++) acc[mt][nt][q] = 0.f;

    const int nch = K >> 5;
    const __half* Agb = A + (size_t)(bm + s_row) * K + s_c * 8;
    const __half* Bgb = B + (size_t)(bn + s_row) * K + s_c * 8;

    // prologue: issue stages 0..2
#pragma unroll
    for (int s = 0; s < 3; s++) {
        const int k0 = s << 5;
        uint32_t ab = sbase + s * STAGE_BYTES;
#pragma unroll
        for (int l = 0; l < 4; l++)
            cp16(ab + (uint32_t)(((s_row + l * 64) * 4 + s_cs) * 16), Agb + (size_t)l * 64 * K + k0);
        uint32_t bb = ab + 16384;
#pragma unroll
        for (int l = 0; l < 2; l++)
            cp16(bb + (uint32_t)(((s_row + l * 64) * 4 + s_cs) * 16), Bgb + (size_t)l * 64 * K + k0);
        CP_COMMIT();
    }
    CP_WAIT2();
    __syncthreads();

    for (int i = 0; i < nch; i++) {
        const int slot = i & 3;
        if (i + 3 < nch) {
            const int k0 = (i + 3) << 5;
            uint32_t ab = sbase + ((i + 3) & 3) * STAGE_BYTES;
#pragma unroll
            for (int l = 0; l < 4; l++)
                cp16(ab + (uint32_t)(((s_row + l * 64) * 4 + s_cs) * 16), Agb + (size_t)l * 64 * K + k0);
            uint32_t bb = ab + 16384;
#pragma unroll
            for (int l = 0; l < 2; l++)
                cp16(bb + (uint32_t)(((s_row + l * 64) * 4 + s_cs) * 16), Bgb + (size_t)l * 64 * K + k0);
        }
        CP_COMMIT();

        const uint32_t* as = (const uint32_t*)(smem + (size_t)slot * STAGE_BYTES);
        const uint32_t* bs = as + 4096;   // B region at +16KB
#pragma unroll
        for (int ks = 0; ks < 2; ks++) {
            const int c0 = ((2 * ks)     ^ swz) * 4 + t;
            const int c1 = ((2 * ks + 1) ^ swz) * 4 + t;
            uint32_t af[4][4], bf[8][2];
#pragma unroll
            for (int mt = 0; mt < 4; mt++) {
                const int rb = (wm * 64 + mt * 16 + g) * 16;
                af[mt][0] = as[rb + c0];
                af[mt][1] = as[rb + 128 + c0];   // row+8
                af[mt][2] = as[rb + c1];
                af[mt][3] = as[rb + 128 + c1];
            }
#pragma unroll
            for (int nt = 0; nt < 8; nt++) {
                const int nb = (wn * 64 + nt * 8 + g) * 16;
                bf[nt][0] = bs[nb + c0];
                bf[nt][1] = bs[nb + c1];
            }
#pragma unroll
            for (int mt = 0; mt < 4; mt++)
#pragma unroll
                for (int nt = 0; nt < 8; nt++)
                    mma_f16(acc[mt][nt], af[mt], bf[nt]);
        }
        CP_WAIT2();
        __syncthreads();
    }

    // ---- epilogue: bias + optional exact GELU; fp16 or fp32 stores ----
    const int do_gelu = flags & 1, out_half = flags & 2;
#pragma unroll
    for (int mt = 0; mt < 4; mt++) {
        const int row = bm + wm * 64 + mt * 16 + g;
#pragma unroll
        for (int nt = 0; nt < 8; nt++) {
            const int col = bn + wn * 64 + nt * 8 + 2 * t;
            const float bz0 = bias[col], bz1 = bias[col + 1];
            float v[4] = { acc[mt][nt][0] + bz0, acc[mt][nt][1] + bz1,
                           acc[mt][nt][2] + bz0, acc[mt][nt][3] + bz1 };
            if (do_gelu) {
#pragma unroll
                for (int q = 0; q < 4; q++)
                    v[q] = 0.5f * v[q] * (1.0f + erff(v[q] * 0.70710678118654752f));
            }
            if (out_half) {
                __half* C = (__half*)Cb + (size_t)blockIdx.z * sC;
                *(__half2*)(C + (size_t)row * N + col)       = __floats2half2_rn(v[0], v[1]);
                *(__half2*)(C + (size_t)(row + 8) * N + col) = __floats2half2_rn(v[2], v[3]);
            } else {
                float* C = (float*)Cb + (size_t)blockIdx.z * sC;
                *(float2*)(C + (size_t)row * N + col)       = make_float2(v[0], v[1]);
                *(float2*)(C + (size_t)(row + 8) * N + col) = make_float2(v[2], v[3]);
            }
        }
    }
}

// ---------------- weight convert + transpose: [E][K][N] fp32 -> [E][N][K] fp16 -------
__global__ void __launch_bounds__(256) convert_w_kernel(const float* __restrict__ in,
                                                        __half* __restrict__ out,
                                                        int K, int N) {
    __shared__ float tile[32][33];
    const float* w = in + (size_t)blockIdx.z * K * N;
    __half* o = out + (size_t)blockIdx.z * N * K;
    int n0 = blockIdx.x * 32, k0 = blockIdx.y * 32;
    int tx = threadIdx.x & 31, ty = threadIdx.x >> 5;   // 32 x 8
#pragma unroll
    for (int i = 0; i < 32; i += 8)
        tile[ty + i][tx] = w[(size_t)(k0 + ty + i) * N + n0 + tx];
    __syncthreads();
#pragma unroll
    for (int i = 0; i < 32; i += 8)
        o[(size_t)(n0 + ty + i) * K + k0 + tx] = __float2half_rn(tile[tx][ty + i]);
}

// ---------------- router: logits -> softmax -> top2 ----------------
__global__ void __launch_bounds__(256) router_kernel(const float* __restrict__ x,
                                                     const float* __restrict__ wr,
                                                     const float* __restrict__ br) {
    __shared__ float swT[NEXP][DMODEL];
    int tid = threadIdx.x;
    for (int i = tid; i < DMODEL * NEXP; i += 256) {
        int d = i >> 3, e = i & 7;
        swT[e][d] = wr[i];
    }
    __syncthreads();
    int warp = tid >> 5, lane = tid & 31;
    int token = blockIdx.x * 8 + warp;
    const float* xr = x + (size_t)token * DMODEL;
    float p[NEXP];
#pragma unroll
    for (int e = 0; e < NEXP; e++) p[e] = 0.f;
    for (int j = lane; j < DMODEL; j += 32) {
        float xv = xr[j];
#pragma unroll
        for (int e = 0; e < NEXP; e++) p[e] = fmaf(xv, swT[e][j], p[e]);
    }
#pragma unroll
    for (int e = 0; e < NEXP; e++) {
#pragma unroll
        for (int off = 16; off; off >>= 1)
            p[e] += __shfl_xor_sync(0xffffffffu, p[e], off);
    }
    if (lane == 0) {
        float mx = -1e30f;
#pragma unroll
        for (int e = 0; e < NEXP; e++) { p[e] += br[e]; mx = fmaxf(mx, p[e]); }
        float s = 0.f;
#pragma unroll
        for (int e = 0; e < NEXP; e++) { p[e] = expf(p[e] - mx); s += p[e]; }
        float inv = 1.f / s;
#pragma unroll
        for (int e = 0; e < NEXP; e++) p[e] *= inv;
        int b0 = 0; float v0 = p[0];
#pragma unroll
        for (int e = 1; e < NEXP; e++) if (p[e] > v0) { v0 = p[e]; b0 = e; }
        int b1 = -1; float v1 = -1.f;
#pragma unroll
        for (int e = 0; e < NEXP; e++) if (e != b0 && p[e] > v1) { v1 = p[e]; b1 = e; }
        g_topi[token*2]   = b0;  g_topv[token*2]   = v0;
        g_topi[token*2+1] = b1;  g_topv[token*2+1] = v1;
    }
}

// ---------------- arrival-order capacity scan (warp-parallel) ----------------
__global__ void __launch_bounds__(1024) scan_kernel() {
    __shared__ int scnt[1024][NEXP];   // 32 KB
    int tid = threadIdx.x, wid = tid >> 5, lane = tid & 31;
#pragma unroll
    for (int e = 0; e < NEXP; e++) scnt[tid][e] = 0;
    int4 vv[8];
#pragma unroll
    for (int q = 0; q < 8; q++) vv[q] = ((const int4*)g_topi)[tid * 8 + q];
#pragma unroll
    for (int q = 0; q < 8; q++) {
        scnt[tid][vv[q].x]++; scnt[tid][vv[q].y]++;
        scnt[tid][vv[q].z]++; scnt[tid][vv[q].w]++;
    }
    __syncthreads();
    if (wid < NEXP) {
        const int e = wid;
        const int j0 = lane * 32;
        int s = 0;
#pragma unroll 8
        for (int j = 0; j < 32; j++) s += scnt[j0 + j][e];
        int x = s;
#pragma unroll
        for (int off = 1; off < 32; off <<= 1) {
            int y = __shfl_up_sync(0xffffffffu, x, off);
            if (lane >= off) x += y;
        }
        int run = x - s;   // exclusive prefix
#pragma unroll 8
        for (int j = 0; j < 32; j++) { int tv = scnt[j0 + j][e]; scnt[j0 + j][e] = run; run += tv; }
        if (lane == 31) g_kept[e] = run < CAP ? run : CAP;
    }
    __syncthreads();
    const int a0 = tid * 32;
#pragma unroll
    for (int q = 0; q < 8; q++) {
        int4 v = vv[q];
        int a = a0 + q * 4;
        int e, pos;
        e = v.x; pos = scnt[tid][e]++;
        if (pos < CAP) { g_apos[a] = pos; g_slot_a[e * CAP + pos] = a; } else g_apos[a] = -1;
        e = v.y; pos = scnt[tid][e]++;
        if (pos < CAP) { g_apos[a+1] = pos; g_slot_a[e * CAP + pos] = a+1; } else g_apos[a+1] = -1;
        e = v.z; pos = scnt[tid][e]++;
        if (pos < CAP) { g_apos[a+2] = pos; g_slot_a[e * CAP + pos] = a+2; } else g_apos[a+2] = -1;
        e = v.w; pos = scnt[tid][e]++;
        if (pos < CAP) { g_apos[a+3] = pos; g_slot_a[e * CAP + pos] = a+3; } else g_apos[a+3] = -1;
    }
}

// ---------------- dispatch gather (fp32 -> fp16 activations) ----------------
__global__ void __launch_bounds__(256) dispatch_kernel(const float* __restrict__ x) {
    int r = blockIdx.x;
    int e = r / CAP, pos = r - e * CAP;
    uint2* dst = (uint2*)(g_buf + (size_t)r * DMODEL);
    if (pos < g_kept[e]) {
        int a = g_slot_a[r];
        float4 v = ((const float4*)(x + (size_t)(a >> 1) * DMODEL))[threadIdx.x];
        __half2 h0 = __floats2half2_rn(v.x, v.y);
        __half2 h1 = __floats2half2_rn(v.z, v.w);
        uint2 u;
        u.x = *reinterpret_cast<uint32_t*>(&h0);
        u.y = *reinterpret_cast<uint32_t*>(&h1);
        dst[threadIdx.x] = u;
    } else {
        dst[threadIdx.x] = make_uint2(0u, 0u);
    }
}

// ---------------- combine ----------------
__global__ void __launch_bounds__(256) combine_kernel(float* __restrict__ out) {
    int token = blockIdx.x;
    int a0 = token * 2;
    int p0 = g_apos[a0], p1 = g_apos[a0 + 1];
    float w0 = (p0 >= 0) ? g_topv[a0]     : 0.f;
    float w1 = (p1 >= 0) ? g_topv[a0 + 1] : 0.f;
    float ws = w0 + w1;
    int t4 = threadIdx.x;
    float4 acc = make_float4(0.f, 0.f, 0.f, 0.f);
    if (p0 >= 0) {
        const float4* r = (const float4*)(g_y + ((size_t)g_topi[a0] * CAP + p0) * DMODEL);
        float4 v = r[t4];
        acc.x = fmaf(w0, v.x, acc.x); acc.y = fmaf(w0, v.y, acc.y);
        acc.z = fmaf(w0, v.z, acc.z); acc.w = fmaf(w0, v.w, acc.w);
    }
    if (p1 >= 0) {
        const float4* r = (const float4*)(g_y + ((size_t)g_topi[a0 + 1] * CAP + p1) * DMODEL);
        float4 v = r[t4];
        acc.x = fmaf(w1, v.x, acc.x); acc.y = fmaf(w1, v.y, acc.y);
        acc.z = fmaf(w1, v.z, acc.z); acc.w = fmaf(w1, v.w, acc.w);
    }
    if (ws > 0.f) {
        float inv = 1.f / fmaxf(ws, 1e-6f);
        acc.x *= inv; acc.y *= inv; acc.z *= inv; acc.w *= inv;
    }
    ((float4*)(out + (size_t)token * DMODEL))[t4] = acc;
}

// ---------------- launch ----------------
#define SMEM_TOTAL (4 * STAGE_BYTES)   // 96 KB

extern "C" void kernel_launch(void* const* d_in, const int* in_sizes, int n_in,
                              void* d_out, int out_size) {
    const float* x  = (const float*)d_in[0];
    const float* wr = (const float*)d_in[1];
    const float* br = (const float*)d_in[2];
    const float* w1 = (const float*)d_in[3];
    const float* b1 = (const float*)d_in[4];
    const float* w2 = (const float*)d_in[5];
    const float* b2 = (const float*)d_in[6];
    float* y = (float*)d_out;

    __half *buf, *h, *w1h, *w2h;
    float *yy;
    cudaGetSymbolAddress((void**)&buf, g_buf);
    cudaGetSymbolAddress((void**)&h,   g_h);
    cudaGetSymbolAddress((void**)&yy,  g_y);
    cudaGetSymbolAddress((void**)&w1h, g_w1h);
    cudaGetSymbolAddress((void**)&w2h, g_w2h);

    cudaFuncSetAttribute(moe_mma_kernel, cudaFuncAttributeMaxDynamicSharedMemorySize, SMEM_TOTAL);

    // weights: fp32 [K][N] -> fp16 [N][K]
    convert_w_kernel<<<dim3(FF / 32, DMODEL / 32, NEXP), 256>>>(w1, w1h, DMODEL, FF);
    convert_w_kernel<<<dim3(DMODEL / 32, FF / 32, NEXP), 256>>>(w2, w2h, FF, DMODEL);

    router_kernel<<<NTOK / 8, 256>>>(x, wr, br);
    scan_kernel<<<1, 1024>>>();
    dispatch_kernel<<<NEXP * CAP, 256>>>(x);

    // GEMM1: h = fp16(GELU(buf @ w1 + b1))   [per expert: 2560x1024 @ 1024x4096]
    dim3 g1(FF / 128, CAP / 256, NEXP);       // 32 x 10 x 8
    moe_mma_kernel<<<g1, 256, SMEM_TOTAL>>>(buf, w1h, b1, (void*)h, FF, DMODEL, 3,
                              (long)CAP * DMODEL, (long)DMODEL * FF, FF, (long)CAP * FF);

    // GEMM2: y_e = h @ w2 + b2 (fp32 out)    [per expert: 2560x4096 @ 4096x1024]
    dim3 g2(DMODEL / 128, CAP / 256, NEXP);   // 8 x 10 x 8
    moe_mma_kernel<<<g2, 256, SMEM_TOTAL>>>(h, w2h, b2, (void*)yy, DMODEL, FF, 0,
                              (long)CAP * FF, (long)FF * DMODEL, DMODEL, (long)CAP * DMODEL);

    combine_kernel<<<NTOK, 256>>>(y);
}

// round 7
// speedup vs baseline: 2.3423x; 1.1424x over previous
#include <cuda_runtime.h>
#include <cuda_fp16.h>
#include <math.h>
#include <stdint.h>

#define NTOK 16384
#define DMODEL 1024
#define FF 4096
#define NEXP 8
#define CAP 2560
#define NA (NTOK*2)

// ---------------- device scratch (static, allocation-free) ----------------
__device__ __half g_buf[(size_t)NEXP*CAP*DMODEL];   //  42 MB dispatched activations (fp16)
__device__ __half g_h  [(size_t)NEXP*CAP*FF];       // 168 MB hidden activations (fp16)
__device__ float  g_y  [(size_t)NEXP*CAP*DMODEL];   //  84 MB expert outputs (fp32)
__device__ __half g_w1h[(size_t)NEXP*DMODEL*FF];    //  64 MB w1 fp16, transposed [E][FF][DMODEL]
__device__ __half g_w2h[(size_t)NEXP*FF*DMODEL];    //  64 MB w2 fp16, transposed [E][DMODEL][FF]
__device__ int   g_topi[NA];
__device__ float g_topv[NA];
__device__ int   g_apos[NA];
__device__ int   g_slot_a[NEXP*CAP];
__device__ int   g_kept[NEXP];

__device__ __forceinline__ void mma_f16(float* d, const uint32_t* a, const uint32_t* b) {
    asm volatile("mma.sync.aligned.m16n8k16.row.col.f32.f16.f16.f32 "
        "{%0,%1,%2,%3}, {%4,%5,%6,%7}, {%8,%9}, {%0,%1,%2,%3};"
        : "+f"(d[0]), "+f"(d[1]), "+f"(d[2]), "+f"(d[3])
        : "r"(a[0]), "r"(a[1]), "r"(a[2]), "r"(a[3]), "r"(b[0]), "r"(b[1]));
}
__device__ __forceinline__ void ldmx4(uint32_t& r0, uint32_t& r1, uint32_t& r2, uint32_t& r3,
                                      uint32_t addr) {
    asm volatile("ldmatrix.sync.aligned.m8n8.x4.shared.b16 {%0,%1,%2,%3}, [%4];"
        : "=r"(r0), "=r"(r1), "=r"(r2), "=r"(r3) : "r"(addr));
}
__device__ __forceinline__ uint32_t smem_u32(const void* p) {
    uint32_t a;
    asm("{ .reg .u64 t; cvta.to.shared.u64 t, %1; cvt.u32.u64 %0, t; }" : "=r"(a) : "l"(p));
    return a;
}
__device__ __forceinline__ void cp16(uint32_t dst, const void* src) {
    asm volatile("cp.async.cg.shared.global [%0], [%1], 16;" :: "r"(dst), "l"(src) : "memory");
}
#define CP_COMMIT() asm volatile("cp.async.commit_group;" ::: "memory")
#define CP_WAIT2()  asm volatile("cp.async.wait_group 2;" ::: "memory")

// ---------------- fp16 tensor-core grouped GEMM, 4-stage cp.async + ldmatrix --------
// C[z] = A[z](MxK rm fp16) @ B[z]^T (B stored [N][K] rm fp16) + bias[z].
// flags: bit0 = exact GELU, bit1 = fp16 output (else fp32).
// CTA tile 256(M)x128(N), k-chunk 32, 8 warps (4m x 2n), warp tile 64x64.
// Stage: A[256 rows][32 fp16] + B[128 rows][32 fp16]; rows = 64B = 4 x 16B chunks,
// chunk c stored at (c ^ ((row>>1)&3)); swizzle has period 8 in rows ->
// every 8-row ldmatrix phase covers all 32 banks (conflict-free).
#define STAGE_BYTES 24576

__global__ void __launch_bounds__(256, 1) moe_mma_kernel(
    const __half* __restrict__ Ab, const __half* __restrict__ Bb,
    const float* __restrict__ biasb, void* __restrict__ Cb,
    int N, int K, int flags,
    long sA, long sB, long sBias, long sC)
{
    extern __shared__ char smem[];
    const uint32_t sbase = smem_u32(smem);

    const __half* A = Ab + (size_t)blockIdx.z * sA;
    const __half* B = Bb + (size_t)blockIdx.z * sB;
    const float* bias = biasb + (size_t)blockIdx.z * sBias;

    const int tid = threadIdx.x;
    const int wid = tid >> 5, lane = tid & 31;
    const int wm = wid >> 1;          // 0..3 -> m offset wm*64
    const int wn = wid & 1;           // 0..1 -> n offset wn*64
    const int g = lane >> 2;          // 0..7
    const int t = lane & 3;           // 0..3
    const int bm = blockIdx.y * 256;
    const int bn = blockIdx.x * 128;

    // staging coords: thread i -> row (i>>2)+l*64, 16B chunk (i&3)
    const int s_row = tid >> 2;
    const int s_c   = tid & 3;
    const int s_cs  = s_c ^ ((s_row >> 1) & 3);

    // ldmatrix coords
    const int lq = lane >> 3;         // matrix id 0..3
    const int lr = lane & 7;
    // A: matrix (q&1) -> m-half(+8), (q>>1) -> k-oct within chunk
    const int a_frow = wm * 64 + ((lq & 1) << 3) + lr;       // + mt*16
    const int a_ks   = lq >> 1;
    const uint32_t a_sw = (a_frow >> 1) & 3;
    // B: matrix (q>>1) -> n-half(+8), (q&1) -> k-oct
    const int b_frow = wn * 64 + ((lq >> 1) << 3) + lr;      // + ntp*16
    const int b_ks   = lq & 1;
    const uint32_t b_sw = (b_frow >> 1) & 3;

    float acc[4][8][4];
#pragma unroll
    for (int mt = 0; mt < 4; mt++)
#pragma unroll
        for (int nt = 0; nt < 8; nt++)
#pragma unroll
            for (int q = 0; q < 4; q++) acc[mt][nt][q] = 0.f;

    const int nch = K >> 5;
    const __half* Agb = A + (size_t)(bm + s_row) * K + s_c * 8;
    const __half* Bgb = B + (size_t)(bn + s_row) * K + s_c * 8;

    // prologue: issue stages 0..2
#pragma unroll
    for (int s = 0; s < 3; s++) {
        const int k0 = s << 5;
        uint32_t ab = sbase + s * STAGE_BYTES;
#pragma unroll
        for (int l = 0; l < 4; l++)
            cp16(ab + (uint32_t)(((s_row + l * 64) * 4 + s_cs) * 16), Agb + (size_t)l * 64 * K + k0);
        uint32_t bb = ab + 16384;
#pragma unroll
        for (int l = 0; l < 2; l++)
            cp16(bb + (uint32_t)(((s_row + l * 64) * 4 + s_cs) * 16), Bgb + (size_t)l * 64 * K + k0);
        CP_COMMIT();
    }
    CP_WAIT2();
    __syncthreads();

    for (int i = 0; i < nch; i++) {
        const int slot = i & 3;
        if (i + 3 < nch) {
            const int k0 = (i + 3) << 5;
            uint32_t ab = sbase + ((i + 3) & 3) * STAGE_BYTES;
#pragma unroll
            for (int l = 0; l < 4; l++)
                cp16(ab + (uint32_t)(((s_row + l * 64) * 4 + s_cs) * 16), Agb + (size_t)l * 64 * K + k0);
            uint32_t bb = ab + 16384;
#pragma unroll
            for (int l = 0; l < 2; l++)
                cp16(bb + (uint32_t)(((s_row + l * 64) * 4 + s_cs) * 16), Bgb + (size_t)l * 64 * K + k0);
        }
        CP_COMMIT();

        const uint32_t abase = sbase + slot * STAGE_BYTES + a_frow * 64;
        const uint32_t bbase = sbase + slot * STAGE_BYTES + 16384 + b_frow * 64;
#pragma unroll
        for (int ks = 0; ks < 2; ks++) {
            const uint32_t a_off = (((uint32_t)(2 * ks + a_ks) ^ a_sw) << 4);
            const uint32_t b_off = (((uint32_t)(2 * ks + b_ks) ^ b_sw) << 4);
            uint32_t af[4][4], bf[8][2];
#pragma unroll
            for (int mt = 0; mt < 4; mt++)
                ldmx4(af[mt][0], af[mt][1], af[mt][2], af[mt][3],
                      abase + mt * 1024 + a_off);
#pragma unroll
            for (int ntp = 0; ntp < 4; ntp++)
                ldmx4(bf[2*ntp][0], bf[2*ntp][1], bf[2*ntp+1][0], bf[2*ntp+1][1],
                      bbase + ntp * 1024 + b_off);
#pragma unroll
            for (int mt = 0; mt < 4; mt++)
#pragma unroll
                for (int nt = 0; nt < 8; nt++)
                    mma_f16(acc[mt][nt], af[mt], bf[nt]);
        }
        CP_WAIT2();
        __syncthreads();
    }

    // ---- epilogue: bias + optional exact GELU; fp16 or fp32 stores ----
    const int do_gelu = flags & 1, out_half = flags & 2;
#pragma unroll
    for (int mt = 0; mt < 4; mt++) {
        const int row = bm + wm * 64 + mt * 16 + g;
#pragma unroll
        for (int nt = 0; nt < 8; nt++) {
            const int col = bn + wn * 64 + nt * 8 + 2 * t;
            const float bz0 = bias[col], bz1 = bias[col + 1];
            float v[4] = { acc[mt][nt][0] + bz0, acc[mt][nt][1] + bz1,
                           acc[mt][nt][2] + bz0, acc[mt][nt][3] + bz1 };
            if (do_gelu) {
#pragma unroll
                for (int q = 0; q < 4; q++)
                    v[q] = 0.5f * v[q] * (1.0f + erff(v[q] * 0.70710678118654752f));
            }
            if (out_half) {
                __half* C = (__half*)Cb + (size_t)blockIdx.z * sC;
                *(__half2*)(C + (size_t)row * N + col)       = __floats2half2_rn(v[0], v[1]);
                *(__half2*)(C + (size_t)(row + 8) * N + col) = __floats2half2_rn(v[2], v[3]);
            } else {
                float* C = (float*)Cb + (size_t)blockIdx.z * sC;
                *(float2*)(C + (size_t)row * N + col)       = make_float2(v[0], v[1]);
                *(float2*)(C + (size_t)(row + 8) * N + col) = make_float2(v[2], v[3]);
            }
        }
    }
}

// ---------------- weight convert + transpose: [E][K][N] fp32 -> [E][N][K] fp16 -------
__global__ void __launch_bounds__(256) convert_w_kernel(const float* __restrict__ in,
                                                        __half* __restrict__ out,
                                                        int K, int N) {
    __shared__ float tile[32][33];
    const float* w = in + (size_t)blockIdx.z * K * N;
    __half* o = out + (size_t)blockIdx.z * N * K;
    int n0 = blockIdx.x * 32, k0 = blockIdx.y * 32;
    int tx = threadIdx.x & 31, ty = threadIdx.x >> 5;   // 32 x 8
#pragma unroll
    for (int i = 0; i < 32; i += 8)
        tile[ty + i][tx] = w[(size_t)(k0 + ty + i) * N + n0 + tx];
    __syncthreads();
#pragma unroll
    for (int i = 0; i < 32; i += 8)
        o[(size_t)(n0 + ty + i) * K + k0 + tx] = __float2half_rn(tile[tx][ty + i]);
}

// ---------------- router: logits -> softmax -> top2 ----------------
__global__ void __launch_bounds__(256) router_kernel(const float* __restrict__ x,
                                                     const float* __restrict__ wr,
                                                     const float* __restrict__ br) {
    __shared__ float swT[NEXP][DMODEL];
    int tid = threadIdx.x;
    for (int i = tid; i < DMODEL * NEXP; i += 256) {
        int d = i >> 3, e = i & 7;
        swT[e][d] = wr[i];
    }
    __syncthreads();
    int warp = tid >> 5, lane = tid & 31;
    int token = blockIdx.x * 8 + warp;
    const float* xr = x + (size_t)token * DMODEL;
    float p[NEXP];
#pragma unroll
    for (int e = 0; e < NEXP; e++) p[e] = 0.f;
    for (int j = lane; j < DMODEL; j += 32) {
        float xv = xr[j];
#pragma unroll
        for (int e = 0; e < NEXP; e++) p[e] = fmaf(xv, swT[e][j], p[e]);
    }
#pragma unroll
    for (int e = 0; e < NEXP; e++) {
#pragma unroll
        for (int off = 16; off; off >>= 1)
            p[e] += __shfl_xor_sync(0xffffffffu, p[e], off);
    }
    if (lane == 0) {
        float mx = -1e30f;
#pragma unroll
        for (int e = 0; e < NEXP; e++) { p[e] += br[e]; mx = fmaxf(mx, p[e]); }
        float s = 0.f;
#pragma unroll
        for (int e = 0; e < NEXP; e++) { p[e] = expf(p[e] - mx); s += p[e]; }
        float inv = 1.f / s;
#pragma unroll
        for (int e = 0; e < NEXP; e++) p[e] *= inv;
        int b0 = 0; float v0 = p[0];
#pragma unroll
        for (int e = 1; e < NEXP; e++) if (p[e] > v0) { v0 = p[e]; b0 = e; }
        int b1 = -1; float v1 = -1.f;
#pragma unroll
        for (int e = 0; e < NEXP; e++) if (e != b0 && p[e] > v1) { v1 = p[e]; b1 = e; }
        g_topi[token*2]   = b0;  g_topv[token*2]   = v0;
        g_topi[token*2+1] = b1;  g_topv[token*2+1] = v1;
    }
}

// ---------------- arrival-order capacity scan (conflict-free, register-packed) -------
__global__ void __launch_bounds__(1024) scan_kernel() {
    __shared__ int scnt[NEXP][1024];   // [e][tid], bank = tid%32 -> conflict-free
    const int tid = threadIdx.x, wid = tid >> 5, lane = tid & 31;

    int4 vv[8];
#pragma unroll
    for (int q = 0; q < 8; q++) vv[q] = ((const int4*)g_topi)[tid * 8 + q];

    // packed histogram: 8 experts x 8 bits in one u64 (max 32 per thread)
    uint64_t hc = 0;
#pragma unroll
    for (int q = 0; q < 8; q++) {
        hc += 1ULL << (vv[q].x * 8);
        hc += 1ULL << (vv[q].y * 8);
        hc += 1ULL << (vv[q].z * 8);
        hc += 1ULL << (vv[q].w * 8);
    }
#pragma unroll
    for (int e = 0; e < NEXP; e++)
        scnt[e][tid] = (int)((hc >> (e * 8)) & 0xff);
    __syncthreads();

    // warp e: exclusive scan over 1024 per-thread counts, coalesced rounds
    if (wid < NEXP) {
        const int e = wid;
        int run = 0;
#pragma unroll 4
        for (int r = 0; r < 32; r++) {
            int v = scnt[e][r * 32 + lane];
            int x = v;
#pragma unroll
            for (int off = 1; off < 32; off <<= 1) {
                int y = __shfl_up_sync(0xffffffffu, x, off);
                if (lane >= off) x += y;
            }
            scnt[e][r * 32 + lane] = run + x - v;     // exclusive prefix
            run += __shfl_sync(0xffffffffu, x, 31);   // round total
        }
        if (lane == 0) g_kept[e] = run < CAP ? run : CAP;
    }
    __syncthreads();

    // scatter with packed 8 x u16 running bases in two u64 registers
    uint64_t b0 = 0, b1 = 0;
#pragma unroll
    for (int e = 0; e < 4; e++) b0 |= (uint64_t)(uint32_t)scnt[e][tid] << (e * 16);
#pragma unroll
    for (int e = 4; e < 8; e++) b1 |= (uint64_t)(uint32_t)scnt[e][tid] << ((e - 4) * 16);

    const int a0 = tid * 32;
#pragma unroll
    for (int q = 0; q < 8; q++) {
        int ids[4] = { vv[q].x, vv[q].y, vv[q].z, vv[q].w };
#pragma unroll
        for (int j = 0; j < 4; j++) {
            const int e = ids[j];
            const int a = a0 + q * 4 + j;
            const int sh = (e & 3) * 16;
            uint64_t w = (e < 4) ? b0 : b1;
            const int pos = (int)((w >> sh) & 0xffff);
            w += 1ULL << sh;
            if (e < 4) b0 = w; else b1 = w;
            if (pos < CAP) { g_apos[a] = pos; g_slot_a[e * CAP + pos] = a; }
            else           { g_apos[a] = -1; }
        }
    }
}

// ---------------- dispatch gather (fp32 -> fp16 activations) ----------------
__global__ void __launch_bounds__(256) dispatch_kernel(const float* __restrict__ x) {
    int r = blockIdx.x;
    int e = r / CAP, pos = r - e * CAP;
    uint2* dst = (uint2*)(g_buf + (size_t)r * DMODEL);
    if (pos < g_kept[e]) {
        int a = g_slot_a[r];
        float4 v = ((const float4*)(x + (size_t)(a >> 1) * DMODEL))[threadIdx.x];
        __half2 h0 = __floats2half2_rn(v.x, v.y);
        __half2 h1 = __floats2half2_rn(v.z, v.w);
        uint2 u;
        u.x = *reinterpret_cast<uint32_t*>(&h0);
        u.y = *reinterpret_cast<uint32_t*>(&h1);
        dst[threadIdx.x] = u;
    } else {
        dst[threadIdx.x] = make_uint2(0u, 0u);
    }
}

// ---------------- combine ----------------
__global__ void __launch_bounds__(256) combine_kernel(float* __restrict__ out) {
    int token = blockIdx.x;
    int a0 = token * 2;
    int p0 = g_apos[a0], p1 = g_apos[a0 + 1];
    float w0 = (p0 >= 0) ? g_topv[a0]     : 0.f;
    float w1 = (p1 >= 0) ? g_topv[a0 + 1] : 0.f;
    float ws = w0 + w1;
    int t4 = threadIdx.x;
    float4 acc = make_float4(0.f, 0.f, 0.f, 0.f);
    if (p0 >= 0) {
        const float4* r = (const float4*)(g_y + ((size_t)g_topi[a0] * CAP + p0) * DMODEL);
        float4 v = r[t4];
        acc.x = fmaf(w0, v.x, acc.x); acc.y = fmaf(w0, v.y, acc.y);
        acc.z = fmaf(w0, v.z, acc.z); acc.w = fmaf(w0, v.w, acc.w);
    }
    if (p1 >= 0) {
        const float4* r = (const float4*)(g_y + ((size_t)g_topi[a0 + 1] * CAP + p1) * DMODEL);
        float4 v = r[t4];
        acc.x = fmaf(w1, v.x, acc.x); acc.y = fmaf(w1, v.y, acc.y);
        acc.z = fmaf(w1, v.z, acc.z); acc.w = fmaf(w1, v.w, acc.w);
    }
    if (ws > 0.f) {
        float inv = 1.f / fmaxf(ws, 1e-6f);
        acc.x *= inv; acc.y *= inv; acc.z *= inv; acc.w *= inv;
    }
    ((float4*)(out + (size_t)token * DMODEL))[t4] = acc;
}

// ---------------- launch ----------------
#define SMEM_TOTAL (4 * STAGE_BYTES)   // 96 KB

extern "C" void kernel_launch(void* const* d_in, const int* in_sizes, int n_in,
                              void* d_out, int out_size) {
    const float* x  = (const float*)d_in[0];
    const float* wr = (const float*)d_in[1];
    const float* br = (const float*)d_in[2];
    const float* w1 = (const float*)d_in[3];
    const float* b1 = (const float*)d_in[4];
    const float* w2 = (const float*)d_in[5];
    const float* b2 = (const float*)d_in[6];
    float* y = (float*)d_out;

    __half *buf, *h, *w1h, *w2h;
    float *yy;
    cudaGetSymbolAddress((void**)&buf, g_buf);
    cudaGetSymbolAddress((void**)&h,   g_h);
    cudaGetSymbolAddress((void**)&yy,  g_y);
    cudaGetSymbolAddress((void**)&w1h, g_w1h);
    cudaGetSymbolAddress((void**)&w2h, g_w2h);

    cudaFuncSetAttribute(moe_mma_kernel, cudaFuncAttributeMaxDynamicSharedMemorySize, SMEM_TOTAL);

    // weights: fp32 [K][N] -> fp16 [N][K]
    convert_w_kernel<<<dim3(FF / 32, DMODEL / 32, NEXP), 256>>>(w1, w1h, DMODEL, FF);
    convert_w_kernel<<<dim3(DMODEL / 32, FF / 32, NEXP), 256>>>(w2, w2h, FF, DMODEL);

    router_kernel<<<NTOK / 8, 256>>>(x, wr, br);
    scan_kernel<<<1, 1024>>>();
    dispatch_kernel<<<NEXP * CAP, 256>>>(x);

    // GEMM1: h = fp16(GELU(buf @ w1 + b1))   [per expert: 2560x1024 @ 1024x4096]
    dim3 g1(FF / 128, CAP / 256, NEXP);       // 32 x 10 x 8
    moe_mma_kernel<<<g1, 256, SMEM_TOTAL>>>(buf, w1h, b1, (void*)h, FF, DMODEL, 3,
                              (long)CAP * DMODEL, (long)DMODEL * FF, FF, (long)CAP * FF);

    // GEMM2: y_e = h @ w2 + b2 (fp32 out)    [per expert: 2560x4096 @ 4096x1024]
    dim3 g2(DMODEL / 128, CAP / 256, NEXP);   // 8 x 10 x 8
    moe_mma_kernel<<<g2, 256, SMEM_TOTAL>>>(h, w2h, b2, (void*)yy, DMODEL, FF, 0,
                              (long)CAP * FF, (long)FF * DMODEL, DMODEL, (long)CAP * DMODEL);

    combine_kernel<<<NTOK, 256>>>(y);
}